// round 1
// baseline (speedup 1.0000x reference)
#include <cuda_runtime.h>
#include <math.h>

// InfoNCE loss: B=131072 rows, D=512 fp32.
// loss = mean_i log(1 + exp((neg_i - pos_i)/T))
//   pos_i = <a,p>/(||a||||p||), neg_i = <a,n>/(||a||||n||)  (norms clamped at 1e-12)
// Pure streaming read of 768 MB -> HBM-bound. One warp per row.

#define D 512
#define TEMPERATURE 1.5f

__global__ void __launch_bounds__(256, 8)
infonce_kernel(const float* __restrict__ a,
               const float* __restrict__ p,
               const float* __restrict__ n,
               float* __restrict__ out,
               int B, float invB)
{
    const int warp_global = (int)((blockIdx.x * (unsigned)blockDim.x + threadIdx.x) >> 5);
    const int lane = threadIdx.x & 31;

    float aa = 0.f, pp = 0.f, nn = 0.f, ap = 0.f, an = 0.f;

    if (warp_global < B) {
        const size_t row_off = (size_t)warp_global * D;
        const float4* __restrict__ a4 = (const float4*)(a + row_off);
        const float4* __restrict__ p4 = (const float4*)(p + row_off);
        const float4* __restrict__ n4 = (const float4*)(n + row_off);

        // D/4 = 128 float4 per row; 32 lanes x 4 iterations. Batch all loads
        // up front per iteration for memory-level parallelism.
        #pragma unroll
        for (int k = 0; k < 4; ++k) {
            const int idx = lane + 32 * k;
            float4 va = a4[idx];
            float4 vp = p4[idx];
            float4 vn = n4[idx];
            aa = fmaf(va.x, va.x, fmaf(va.y, va.y, fmaf(va.z, va.z, fmaf(va.w, va.w, aa))));
            pp = fmaf(vp.x, vp.x, fmaf(vp.y, vp.y, fmaf(vp.z, vp.z, fmaf(vp.w, vp.w, pp))));
            nn = fmaf(vn.x, vn.x, fmaf(vn.y, vn.y, fmaf(vn.z, vn.z, fmaf(vn.w, vn.w, nn))));
            ap = fmaf(va.x, vp.x, fmaf(va.y, vp.y, fmaf(va.z, vp.z, fmaf(va.w, vp.w, ap))));
            an = fmaf(va.x, vn.x, fmaf(va.y, vn.y, fmaf(va.z, vn.z, fmaf(va.w, vn.w, an))));
        }
    }

    // Warp tree-reduction of the 5 partial sums.
    #pragma unroll
    for (int off = 16; off > 0; off >>= 1) {
        aa += __shfl_xor_sync(0xFFFFFFFFu, aa, off);
        pp += __shfl_xor_sync(0xFFFFFFFFu, pp, off);
        nn += __shfl_xor_sync(0xFFFFFFFFu, nn, off);
        ap += __shfl_xor_sync(0xFFFFFFFFu, ap, off);
        an += __shfl_xor_sync(0xFFFFFFFFu, an, off);
    }

    float partial = 0.f;
    if (lane == 0 && warp_global < B) {
        const float na  = fmaxf(sqrtf(aa), 1e-12f);
        const float npo = fmaxf(sqrtf(pp), 1e-12f);
        const float nne = fmaxf(sqrtf(nn), 1e-12f);
        const float pos = ap / (na * npo);
        const float neg = an / (na * nne);
        const float z = (neg - pos) * (1.0f / TEMPERATURE);
        // -log_softmax[0] = log(1 + exp(z)); z in [-1.34, 1.34] -> no overflow
        partial = log1pf(expf(z)) * invB;
    }

    // Block reduction (8 warps) then a single atomic per block.
    __shared__ float s[8];
    const int wid = threadIdx.x >> 5;
    if (lane == 0) s[wid] = partial;
    __syncthreads();
    if (threadIdx.x == 0) {
        float sum = s[0];
        #pragma unroll
        for (int i = 1; i < 8; ++i) sum += s[i];
        atomicAdd(out, sum);
    }
}

extern "C" void kernel_launch(void* const* d_in, const int* in_sizes, int n_in,
                              void* d_out, int out_size)
{
    const float* anchors   = (const float*)d_in[0];
    const float* positives = (const float*)d_in[1];
    const float* negatives = (const float*)d_in[2];
    float* out = (float*)d_out;

    const int B = in_sizes[0] / D;

    cudaMemsetAsync(out, 0, sizeof(float));

    const int threads = 256;               // 8 warps = 8 rows per block
    const int blocks = (B + 7) / 8;
    infonce_kernel<<<blocks, threads>>>(anchors, positives, negatives, out,
                                        B, 1.0f / (float)B);
}